// round 14
// baseline (speedup 1.0000x reference)
#include <cuda_runtime.h>
#include <cuda_bf16.h>
#include <cstdint>
#include <math.h>

#define EPS 1e-8f

// Scratch (device globals: no allocation allowed)
__device__ float g_att[2][16][128][128];       // attention matrices (fw/bw)
__device__ float g_rowsum_fw[16][128];         // sum_j att_fw[b,i,j]
__device__ float g_meanS[2][16][128][256];     // att @ q2 (unnormalized mean)
__device__ float g_maxat[2][16][128][256];     // max_j att[i,j]*q2[j,h]
__device__ __nv_bfloat16 g_q1h[16 * 128 * 512];  // q1 hi bf16
__device__ __nv_bfloat16 g_q1l[16 * 128 * 512];  // q1 lo bf16
__device__ __nv_bfloat16 g_q2h[16 * 128 * 512];  // q2 hi bf16
__device__ __nv_bfloat16 g_q2l[16 * 128 * 512];  // q2 lo bf16

// ---------------------------------------------------------------------------
// mma.sync m16n8k16 bf16 (HMMA path — legal on plain sm_103 PTX target)
// ---------------------------------------------------------------------------
__device__ __forceinline__ void mma16816(float* d, const uint32_t* a, const uint32_t* b) {
    asm volatile(
        "mma.sync.aligned.m16n8k16.row.col.f32.bf16.bf16.f32 "
        "{%0,%1,%2,%3}, {%4,%5,%6,%7}, {%8,%9}, {%0,%1,%2,%3};"
        : "+f"(d[0]), "+f"(d[1]), "+f"(d[2]), "+f"(d[3])
        : "r"(a[0]), "r"(a[1]), "r"(a[2]), "r"(a[3]), "r"(b[0]), "r"(b[1]));
}

__device__ __forceinline__ uint32_t smem_u32(const void* p) {
    return (uint32_t)__cvta_generic_to_shared(p);
}
#define CP_ASYNC8(dst_u32, src_ptr) \
    asm volatile("cp.async.ca.shared.global [%0], [%1], 8;" \
        :: "r"(dst_u32), "l"(src_ptr))
#define CP_ASYNC_COMMIT() asm volatile("cp.async.commit_group;" ::: "memory")
#define CP_ASYNC_WAIT0()  asm volatile("cp.async.wait_group 0;" ::: "memory")

// ---------------------------------------------------------------------------
// Kernel 0: split q1 AND q2 into hi/lo bf16 (done once)
// ---------------------------------------------------------------------------
__global__ void k_split(const float* __restrict__ q1, const float* __restrict__ q2) {
    int gidx = blockIdx.x * 256 + threadIdx.x;   // 0 .. 524287
    int which = gidx >> 18;                      // 0 = q1, 1 = q2
    int idx = gidx & 0x3FFFF;                    // 0 .. 262143 float4 groups
    const float* src = which ? q2 : q1;
    float4 v = *(const float4*)(src + (size_t)idx * 4);
    __nv_bfloat16 h0 = __float2bfloat16(v.x), h1 = __float2bfloat16(v.y);
    __nv_bfloat16 h2 = __float2bfloat16(v.z), h3 = __float2bfloat16(v.w);
    __nv_bfloat16 l0 = __float2bfloat16(v.x - __bfloat162float(h0));
    __nv_bfloat16 l1 = __float2bfloat16(v.y - __bfloat162float(h1));
    __nv_bfloat16 l2 = __float2bfloat16(v.z - __bfloat162float(h2));
    __nv_bfloat16 l3 = __float2bfloat16(v.w - __bfloat162float(h3));
    uint2 pk;
    pk.x = ((uint32_t)__bfloat16_as_ushort(h1) << 16) | __bfloat16_as_ushort(h0);
    pk.y = ((uint32_t)__bfloat16_as_ushort(h3) << 16) | __bfloat16_as_ushort(h2);
    ((uint2*)(which ? g_q2h : g_q1h))[idx] = pk;
    pk.x = ((uint32_t)__bfloat16_as_ushort(l1) << 16) | __bfloat16_as_ushort(l0);
    pk.y = ((uint32_t)__bfloat16_as_ushort(l3) << 16) | __bfloat16_as_ushort(l2);
    ((uint2*)(which ? g_q2l : g_q1l))[idx] = pk;
}

// ---------------------------------------------------------------------------
// Shared tile geometry
// ---------------------------------------------------------------------------
#define TS_W    36                       // padded tile stride in 32-bit words
#define TILE_B  (128 * TS_W * 4)         // 18432 bytes (128-row tile)
#define TILE64_B (64 * TS_W * 4)         // 9216 bytes (64-row tile)
#define TILE32_B (32 * TS_W * 4)         // 4608 bytes (32-row tile)

// ---------------------------------------------------------------------------
// Kernel 1 (HMMA): attention + fused rowsum. M split 4 ways.
// grid (16 b, 2 dir, 4 ms). CTA tile 32x128. 8 warps, each 32x16.
// ---------------------------------------------------------------------------
#define AOFF_N1   0
#define AOFF_N2   256
#define AOFF_RED  1024
#define AOFF_AH   3072
#define AOFF_AL   (AOFF_AH + TILE32_B)
#define AOFF_BH   (AOFF_AH + 2 * TILE32_B)
#define AOFF_BL   (AOFF_AH + 2 * TILE32_B + TILE_B)
#define SMEM_ATT_TOTAL (AOFF_AH + 2 * TILE32_B + 2 * TILE_B)   // 49152

__global__ void __launch_bounds__(256)
k_attention_mma(const float* __restrict__ q1, const float* __restrict__ q2) {
    extern __shared__ char smem[];
    int b = blockIdx.x, dir = blockIdx.y, ms = blockIdx.z;
    int m0 = ms * 32;
    int t = threadIdx.x;
    int wid = t >> 5, lane = t & 31;
    int gid = lane >> 2, tig = lane & 3;
    int nbw = wid * 16;                   // warp col base (8 warps x 16 cols)

    const float* Ag = q1 + ((size_t)b * 128 + m0) * 512 + dir * 256;
    const float* Bg = q2 + (size_t)b * 65536 + dir * 256;

    float* n1_s = (float*)(smem + AOFF_N1);      // [32]
    float* n2_s = (float*)(smem + AOFF_N2);      // [128]
    float* red  = (float*)(smem + AOFF_RED);     // [32][8]
    uint32_t* Ah_w = (uint32_t*)(smem + AOFF_AH);
    uint32_t* Al_w = (uint32_t*)(smem + AOFF_AL);
    uint32_t* Bh_w = (uint32_t*)(smem + AOFF_BH);
    uint32_t* Bl_w = (uint32_t*)(smem + AOFF_BL);

    // exact fp32 norms: t<128 -> q2 rows (n2), t in [128,160) -> q1 rows (n1)
    if (t < 160) {
        int r = (t < 128) ? t : (t - 128);
        const float* src = (t < 128) ? (Bg + (size_t)r * 512) : (Ag + (size_t)r * 512);
        float s = 0.f;
        for (int h = 0; h < 256; h += 4) {
            float4 v = *(const float4*)(src + h);
            s += v.x * v.x + v.y * v.y + v.z * v.z + v.w * v.w;
        }
        if (t < 128) n2_s[r] = sqrtf(s); else n1_s[r] = sqrtf(s);
    }

    float acc[2][2][4] = {};

    const __nv_bfloat16* q1h_base = g_q1h + ((size_t)b * 128 + m0) * 512 + dir * 256;
    const __nv_bfloat16* q1l_base = g_q1l + ((size_t)b * 128 + m0) * 512 + dir * 256;
    const __nv_bfloat16* q2h_base = g_q2h + ((size_t)b * 128) * 512 + dir * 256;
    const __nv_bfloat16* q2l_base = g_q2l + ((size_t)b * 128) * 512 + dir * 256;

    for (int c = 0; c < 4; c++) {
        int kb = c * 64;
        // A chunk: 32 rows x 64 cols = 512 uint2 (cp.async)
#pragma unroll
        for (int r = 0; r < 2; r++) {
            int v = r * 256 + t;
            int n = v >> 4;
            int kk = (v & 15) * 4;
            uint32_t woff = (uint32_t)n * TS_W + (uint32_t)(kk >> 1);
            CP_ASYNC8(smem_u32(Ah_w + woff), q1h_base + (size_t)n * 512 + kb + kk);
            CP_ASYNC8(smem_u32(Al_w + woff), q1l_base + (size_t)n * 512 + kb + kk);
        }
        // B chunk: 128 rows x 64 cols = 2048 uint2 (cp.async)
#pragma unroll
        for (int r = 0; r < 8; r++) {
            int v = r * 256 + t;
            int n = v >> 4;
            int kk = (v & 15) * 4;
            uint32_t woff = (uint32_t)n * TS_W + (uint32_t)(kk >> 1);
            CP_ASYNC8(smem_u32(Bh_w + woff), q2h_base + (size_t)n * 512 + kb + kk);
            CP_ASYNC8(smem_u32(Bl_w + woff), q2l_base + (size_t)n * 512 + kb + kk);
        }
        CP_ASYNC_COMMIT();
        CP_ASYNC_WAIT0();
        __syncthreads();

#pragma unroll
        for (int ks = 0; ks < 4; ks++) {
            int kw = ks * 8;
            uint32_t bhf[2][2], blf[2][2];
#pragma unroll
            for (int ni = 0; ni < 2; ni++) {
                const uint32_t* ph = Bh_w + (uint32_t)(nbw + ni * 8 + gid) * TS_W + kw + tig;
                bhf[ni][0] = ph[0]; bhf[ni][1] = ph[4];
                const uint32_t* pl = Bl_w + (uint32_t)(nbw + ni * 8 + gid) * TS_W + kw + tig;
                blf[ni][0] = pl[0]; blf[ni][1] = pl[4];
            }
#pragma unroll
            for (int mi = 0; mi < 2; mi++) {
                const uint32_t* pa = Ah_w + (uint32_t)(mi * 16 + gid) * TS_W + kw + tig;
                uint32_t ah[4];
                ah[0] = pa[0]; ah[1] = pa[8 * TS_W];
                ah[2] = pa[4]; ah[3] = pa[8 * TS_W + 4];
                const uint32_t* pl = Al_w + (uint32_t)(mi * 16 + gid) * TS_W + kw + tig;
                uint32_t al[4];
                al[0] = pl[0]; al[1] = pl[8 * TS_W];
                al[2] = pl[4]; al[3] = pl[8 * TS_W + 4];
#pragma unroll
                for (int ni = 0; ni < 2; ni++) {
                    mma16816(acc[mi][ni], ah, bhf[ni]);
                    mma16816(acc[mi][ni], ah, blf[ni]);
                    mma16816(acc[mi][ni], al, bhf[ni]);
                }
            }
        }
        __syncthreads();
    }

    // ---- epilogue: normalize, store att, fused rowsum ----
    float n2v[2][2];
#pragma unroll
    for (int ni = 0; ni < 2; ni++) {
        int cb = nbw + ni * 8 + 2 * tig;
        n2v[ni][0] = n2_s[cb];
        n2v[ni][1] = n2_s[cb + 1];
    }
#pragma unroll
    for (int mi = 0; mi < 2; mi++) {
        int rloc = mi * 16 + gid;
        float na0 = n1_s[rloc], na1 = n1_s[rloc + 8];
        float s0 = 0.f, s1 = 0.f;
#pragma unroll
        for (int ni = 0; ni < 2; ni++) {
            int cb = nbw + ni * 8 + 2 * tig;
            float d00 = na0 * n2v[ni][0]; d00 = (d00 > EPS) ? d00 : EPS;
            float d01 = na0 * n2v[ni][1]; d01 = (d01 > EPS) ? d01 : EPS;
            float d10 = na1 * n2v[ni][0]; d10 = (d10 > EPS) ? d10 : EPS;
            float d11 = na1 * n2v[ni][1]; d11 = (d11 > EPS) ? d11 : EPS;
            float a00 = acc[mi][ni][0] / d00;
            float a01 = acc[mi][ni][1] / d01;
            float a10 = acc[mi][ni][2] / d10;
            float a11 = acc[mi][ni][3] / d11;
            *(float2*)&g_att[dir][b][m0 + rloc][cb]     = make_float2(a00, a01);
            *(float2*)&g_att[dir][b][m0 + rloc + 8][cb] = make_float2(a10, a11);
            s0 += a00 + a01;
            s1 += a10 + a11;
        }
        s0 += __shfl_xor_sync(0xffffffffu, s0, 1);
        s0 += __shfl_xor_sync(0xffffffffu, s0, 2);
        s1 += __shfl_xor_sync(0xffffffffu, s1, 1);
        s1 += __shfl_xor_sync(0xffffffffu, s1, 2);
        if (tig == 0) {
            red[rloc * 8 + wid] = s0;
            red[(rloc + 8) * 8 + wid] = s1;
        }
    }
    __syncthreads();
    if (dir == 0 && t < 32) {
        float s = 0.f;
#pragma unroll
        for (int w = 0; w < 8; w++) s += red[t * 8 + w];
        g_rowsum_fw[b][m0 + t] = s;
    }
}

// ---------------------------------------------------------------------------
// Kernel 2: meanS / maxat — j-outer, register accumulators.
// ---------------------------------------------------------------------------
__global__ void __launch_bounds__(256)
k_meanmax(const float* __restrict__ q2) {
    int b = blockIdx.x, dir = blockIdx.y, iq = blockIdx.z;
    int i0 = iq * 8;
    __shared__ float2 att_s[8][64];

    const float* src = &g_att[dir][b][i0][0];
    {
        int c = threadIdx.x;
        float4 v0 = *(const float4*)(src + c * 4);
        ((float4*)att_s)[c] = v0;
    }
    __syncthreads();

    int h = threadIdx.x;
    const float* B = q2 + (size_t)b * 65536 + dir * 256 + h;

    float acc[8] = {};
    float mx[8] = {-INFINITY, -INFINITY, -INFINITY, -INFINITY,
                   -INFINITY, -INFINITY, -INFINITY, -INFINITY};

#pragma unroll 4
    for (int j2 = 0; j2 < 64; j2++) {
        float q0 = __ldg(B + (size_t)(2 * j2) * 512);
        float q1 = __ldg(B + (size_t)(2 * j2 + 1) * 512);
#pragma unroll
        for (int i = 0; i < 8; i++) {
            float2 a = att_s[i][j2];
            float v0 = a.x * q0;
            float v1 = a.y * q1;
            acc[i] += v0 + v1;
            mx[i] = fmaxf(mx[i], fmaxf(v0, v1));
        }
    }

#pragma unroll
    for (int i = 0; i < 8; i++) {
        g_meanS[dir][b][i0 + i][h] = acc[i];
        g_maxat[dir][b][i0 + i][h] = mx[i];
    }
}

// ---------------------------------------------------------------------------
// Kernel 3 (HMMA): cos_maxpool. CTA = (b, p, dir, mh): M=64 rows, N=128, K=256.
// grid (16, 16, 4) = 1024 CTAs, 3 CTAs/SM. cp.async B copy overlapped with
// A conversion.
// ---------------------------------------------------------------------------
#define OFF_W2   0
#define OFF_NA   1024
#define OFF_NC   1280
#define OFF_RED  1792
#define OFF_AH   3072
#define OFF_AL   (OFF_AH + TILE64_B)
#define OFF_BH   (OFF_AH + 2 * TILE64_B)
#define OFF_BL   (OFF_AH + 2 * TILE64_B + TILE_B)
#define SMEM_MMA_TOTAL (OFF_AH + 2 * TILE64_B + 2 * TILE_B)   // 58368

__global__ void __launch_bounds__(256, 3)
k_maxpool_mma(const float* __restrict__ q1, const float* __restrict__ q2,
              const float* __restrict__ W, float* __restrict__ out) {
    extern __shared__ char smem[];
    int b = blockIdx.x, p = blockIdx.y;
    int dir = blockIdx.z >> 1, mh = blockIdx.z & 1;
    int m0 = mh * 64;
    int t = threadIdx.x;
    int wid = t >> 5, lane = t & 31;
    int gid = lane >> 2, tig = lane & 3;
    int wr = wid >> 2, wc = wid & 3;       // warp grid 2 (M) x 4 (N)
    int mb = wr * 32, nb = wc * 32;

    const float* Ag = q1 + ((size_t)b * 128 + m0) * 512 + dir * 256;
    const float* Bg = q2 + (size_t)b * 65536 + dir * 256;
    const float* Wp = W + (size_t)((2 + dir) * 16 + p) * 256;

    float* w2s  = (float*)(smem + OFF_W2);
    float* na_s = (float*)(smem + OFF_NA);       // [64]
    float* nc_s = (float*)(smem + OFF_NC);       // [128]
    float* red  = (float*)(smem + OFF_RED);      // [64][4]
    uint32_t* Ah_w = (uint32_t*)(smem + OFF_AH);
    uint32_t* Al_w = (uint32_t*)(smem + OFF_AL);
    uint32_t* Bh_w = (uint32_t*)(smem + OFF_BH);
    uint32_t* Bl_w = (uint32_t*)(smem + OFF_BL);

    { float w = Wp[t]; w2s[t] = w * w; }
    __syncthreads();

    // exact fp32 weighted norms: t<128 -> nc (q2 rows), t in [128,192) -> na
    if (t < 192) {
        int r = (t < 128) ? t : (t - 128);
        const float* src = (t < 128) ? (Bg + (size_t)r * 512) : (Ag + (size_t)r * 512);
        float s = 0.f;
        for (int h = 0; h < 256; h += 4) {
            float4 v = *(const float4*)(src + h);
            s += v.x * v.x * w2s[h] + v.y * v.y * w2s[h + 1]
               + v.z * v.z * w2s[h + 2] + v.w * v.w * w2s[h + 3];
        }
        if (t < 128) nc_s[r] = sqrtf(s); else na_s[r] = sqrtf(s);
    }

    float acc[2][4][4];
#pragma unroll
    for (int mi = 0; mi < 2; mi++)
#pragma unroll
        for (int ni = 0; ni < 4; ni++)
#pragma unroll
            for (int c = 0; c < 4; c++) acc[mi][ni][c] = 0.f;

    const __nv_bfloat16* q2h_base = g_q2h + ((size_t)b * 128) * 512 + dir * 256;
    const __nv_bfloat16* q2l_base = g_q2l + ((size_t)b * 128) * 512 + dir * 256;

    for (int c = 0; c < 4; c++) {
        int kb = c * 64;
        // ---- issue cp.async for B chunk first (overlaps with A convert) ----
#pragma unroll
        for (int r = 0; r < 8; r++) {
            int v = r * 256 + t;
            int n = v >> 4;
            int kk = (v & 15) * 4;
            uint32_t woff = (uint32_t)n * TS_W + (uint32_t)(kk >> 1);
            CP_ASYNC8(smem_u32(Bh_w + woff), q2h_base + (size_t)n * 512 + kb + kk);
            CP_ASYNC8(smem_u32(Bl_w + woff), q2l_base + (size_t)n * 512 + kb + kk);
        }
        CP_ASYNC_COMMIT();

        // ---- convert A chunk (q1 .* w2), split hi/lo: 64 rows x 64 cols ----
#pragma unroll
        for (int r = 0; r < 4; r++) {
            int v = r * 256 + t;             // 0..1023
            int i = v >> 4;                  // row 0..63
            int h4 = (v & 15) * 4;
            float4 qa = *(const float4*)(Ag + (size_t)i * 512 + kb + h4);
            float a0 = qa.x * w2s[kb + h4 + 0];
            float a1 = qa.y * w2s[kb + h4 + 1];
            float a2 = qa.z * w2s[kb + h4 + 2];
            float a3 = qa.w * w2s[kb + h4 + 3];
            __nv_bfloat16 h0 = __float2bfloat16(a0), h1 = __float2bfloat16(a1);
            __nv_bfloat16 h2 = __float2bfloat16(a2), h3 = __float2bfloat16(a3);
            __nv_bfloat16 l0 = __float2bfloat16(a0 - __bfloat162float(h0));
            __nv_bfloat16 l1 = __float2bfloat16(a1 - __bfloat162float(h1));
            __nv_bfloat16 l2 = __float2bfloat16(a2 - __bfloat162float(h2));
            __nv_bfloat16 l3 = __float2bfloat16(a3 - __bfloat162float(h3));
            uint32_t woff = (uint32_t)i * TS_W + (uint32_t)(h4 >> 1);
            uint2 pk;
            pk.x = ((uint32_t)__bfloat16_as_ushort(h1) << 16) | __bfloat16_as_ushort(h0);
            pk.y = ((uint32_t)__bfloat16_as_ushort(h3) << 16) | __bfloat16_as_ushort(h2);
            *(uint2*)(Ah_w + woff) = pk;
            pk.x = ((uint32_t)__bfloat16_as_ushort(l1) << 16) | __bfloat16_as_ushort(l0);
            pk.y = ((uint32_t)__bfloat16_as_ushort(l3) << 16) | __bfloat16_as_ushort(l2);
            *(uint2*)(Al_w + woff) = pk;
        }
        CP_ASYNC_WAIT0();
        __syncthreads();

        // ---- MMA over this chunk: 4 k-steps of 16 ----
#pragma unroll
        for (int ks = 0; ks < 4; ks++) {
            int kw = ks * 8;
            uint32_t bhf[4][2], blf[4][2];
#pragma unroll
            for (int ni = 0; ni < 4; ni++) {
                const uint32_t* ph = Bh_w + (uint32_t)(nb + ni * 8 + gid) * TS_W + kw + tig;
                bhf[ni][0] = ph[0]; bhf[ni][1] = ph[4];
                const uint32_t* pl = Bl_w + (uint32_t)(nb + ni * 8 + gid) * TS_W + kw + tig;
                blf[ni][0] = pl[0]; blf[ni][1] = pl[4];
            }
#pragma unroll
            for (int mi = 0; mi < 2; mi++) {
                const uint32_t* pa = Ah_w + (uint32_t)(mb + mi * 16 + gid) * TS_W + kw + tig;
                uint32_t ah[4];
                ah[0] = pa[0]; ah[1] = pa[8 * TS_W];
                ah[2] = pa[4]; ah[3] = pa[8 * TS_W + 4];
                const uint32_t* pl = Al_w + (uint32_t)(mb + mi * 16 + gid) * TS_W + kw + tig;
                uint32_t al[4];
                al[0] = pl[0]; al[1] = pl[8 * TS_W];
                al[2] = pl[4]; al[3] = pl[8 * TS_W + 4];
#pragma unroll
                for (int ni = 0; ni < 4; ni++) {
                    mma16816(acc[mi][ni], ah, bhf[ni]);
                    mma16816(acc[mi][ni], ah, blf[ni]);
                    mma16816(acc[mi][ni], al, bhf[ni]);
                }
            }
        }
        __syncthreads();
    }

    // ---- epilogue: cos divide + row max ----
    float nc_v[4][2];
#pragma unroll
    for (int ni = 0; ni < 4; ni++) {
        int cb = nb + ni * 8 + 2 * tig;
        nc_v[ni][0] = nc_s[cb];
        nc_v[ni][1] = nc_s[cb + 1];
    }
#pragma unroll
    for (int mi = 0; mi < 2; mi++) {
        int r0 = mb + mi * 16 + gid;       // 0..63 local
        float na0 = na_s[r0], na1 = na_s[r0 + 8];
        float m0v = -INFINITY, m1v = -INFINITY;
#pragma unroll
        for (int ni = 0; ni < 4; ni++) {
            m0v = fmaxf(m0v, acc[mi][ni][0] / fmaxf(na0 * nc_v[ni][0], EPS));
            m0v = fmaxf(m0v, acc[mi][ni][1] / fmaxf(na0 * nc_v[ni][1], EPS));
            m1v = fmaxf(m1v, acc[mi][ni][2] / fmaxf(na1 * nc_v[ni][0], EPS));
            m1v = fmaxf(m1v, acc[mi][ni][3] / fmaxf(na1 * nc_v[ni][1], EPS));
        }
        m0v = fmaxf(m0v, __shfl_xor_sync(0xffffffffu, m0v, 1));
        m0v = fmaxf(m0v, __shfl_xor_sync(0xffffffffu, m0v, 2));
        m1v = fmaxf(m1v, __shfl_xor_sync(0xffffffffu, m1v, 1));
        m1v = fmaxf(m1v, __shfl_xor_sync(0xffffffffu, m1v, 2));
        if (tig == 0) {
            red[r0 * 4 + wc] = m0v;
            red[(r0 + 8) * 4 + wc] = m1v;
        }
    }
    __syncthreads();
    if (t < 64) {
        float m = red[t * 4 + 0];
        m = fmaxf(m, red[t * 4 + 1]);
        m = fmaxf(m, red[t * 4 + 2]);
        m = fmaxf(m, red[t * 4 + 3]);
        out[((size_t)b * 128 + m0 + t) * 128 + 32 + dir * 16 + p] = m;
    }
}

// ---------------------------------------------------------------------------
// Kernel 4: the six cos_full outputs
// ---------------------------------------------------------------------------
__global__ void k_cosfull(const float* __restrict__ q1, const float* __restrict__ q2,
                          const float* __restrict__ W, float* __restrict__ out) {
    int i = blockIdx.x, b = blockIdx.y;
    int lane = threadIdx.x & 31, warp = threadIdx.x >> 5;

    for (int s = 0; s < 12; s++) {
        int tk = warp + 8 * s;
        int p = tk & 15;
        int rest = tk >> 4;
        int dir = rest & 1, which = rest >> 1;
        int widx = (which == 0) ? dir : ((which == 1) ? 4 + dir : 6 + dir);
        const float* wv = W + (size_t)(widx * 16 + p) * 256;
        const float* x  = q1 + (size_t)b * 65536 + (size_t)i * 512 + dir * 256;
        const float* y;
        float sy = 1.f;
        if (which == 0) {
            int j = (dir == 0) ? 127 : 0;
            y = q2 + (size_t)b * 65536 + (size_t)j * 512 + dir * 256;
        } else if (which == 1) {
            y = &g_meanS[dir][b][i][0];
            float rs = g_rowsum_fw[b][i];
            float bsafe = (rs > EPS) ? rs : EPS;
            sy = 1.f / bsafe;
        } else {
            y = &g_maxat[dir][b][i][0];
        }

        float sxy = 0.f, sxx = 0.f, syy = 0.f;
        for (int h = lane; h < 256; h += 32) {
            float w = wv[h]; float ww = w * w;
            float xv = x[h];
            float yv = y[h] * sy;
            sxy += xv * yv * ww;
            sxx += xv * xv * ww;
            syy += yv * yv * ww;
        }
#pragma unroll
        for (int off = 16; off > 0; off >>= 1) {
            sxy += __shfl_xor_sync(0xffffffffu, sxy, off);
            sxx += __shfl_xor_sync(0xffffffffu, sxx, off);
            syy += __shfl_xor_sync(0xffffffffu, syy, off);
        }
        if (lane == 0) {
            float den = fmaxf(sqrtf(sxx) * sqrtf(syy), EPS);
            int col = ((which == 0) ? 0 : (which == 1) ? 64 : 96) + dir * 16 + p;
            out[((size_t)b * 128 + i) * 128 + col] = sxy / den;
        }
    }
}

// ---------------------------------------------------------------------------
extern "C" void kernel_launch(void* const* d_in, const int* in_sizes, int n_in,
                              void* d_out, int out_size) {
    const float* q1 = (const float*)d_in[0];
    const float* q2 = (const float*)d_in[1];
    const float* W  = (const float*)d_in[2];
    float* out = (float*)d_out;

    cudaFuncSetAttribute(k_attention_mma, cudaFuncAttributeMaxDynamicSharedMemorySize,
                         SMEM_ATT_TOTAL);
    cudaFuncSetAttribute(k_maxpool_mma, cudaFuncAttributeMaxDynamicSharedMemorySize,
                         SMEM_MMA_TOTAL);

    k_split<<<2048, 256>>>(q1, q2);
    k_attention_mma<<<dim3(16, 2, 4), 256, SMEM_ATT_TOTAL>>>(q1, q2);
    k_meanmax<<<dim3(16, 2, 16), 256>>>(q2);
    k_maxpool_mma<<<dim3(16, 16, 4), 256, SMEM_MMA_TOTAL>>>(q1, q2, W, out);
    k_cosfull<<<dim3(128, 16), 256>>>(q1, q2, W, out);
}

// round 16
// speedup vs baseline: 1.2564x; 1.2564x over previous
#include <cuda_runtime.h>
#include <cuda_bf16.h>
#include <cstdint>
#include <math.h>

#define EPS 1e-8f

// Scratch (device globals: no allocation allowed)
__device__ float g_att[2][16][128][128];       // attention matrices (fw/bw)
__device__ float g_rowsum_fw[16][128];         // sum_j att_fw[b,i,j]
__device__ float g_meanS[2][16][128][256];     // att @ q2 (unnormalized mean)
__device__ float g_maxat[2][16][128][256];     // max_j att[i,j]*q2[j,h]
__device__ __nv_bfloat16 g_q1h[16 * 128 * 512];  // q1 hi bf16
__device__ __nv_bfloat16 g_q1l[16 * 128 * 512];  // q1 lo bf16
__device__ __nv_bfloat16 g_q2h[16 * 128 * 512];  // q2 hi bf16
__device__ __nv_bfloat16 g_q2l[16 * 128 * 512];  // q2 lo bf16
// Precomputed norms
__device__ float g_wn1[2][16][16][128];        // [dir][p][b][i] weighted q1 norms
__device__ float g_wn2[2][16][16][128];        // [dir][p][b][j] weighted q2 norms
__device__ float g_n1[2][16][128];             // unweighted q1 norms
__device__ float g_n2[2][16][128];             // unweighted q2 norms

// ---------------------------------------------------------------------------
// mma.sync m16n8k16 bf16 (HMMA path — legal on plain sm_103 PTX target)
// ---------------------------------------------------------------------------
__device__ __forceinline__ void mma16816(float* d, const uint32_t* a, const uint32_t* b) {
    asm volatile(
        "mma.sync.aligned.m16n8k16.row.col.f32.bf16.bf16.f32 "
        "{%0,%1,%2,%3}, {%4,%5,%6,%7}, {%8,%9}, {%0,%1,%2,%3};"
        : "+f"(d[0]), "+f"(d[1]), "+f"(d[2]), "+f"(d[3])
        : "r"(a[0]), "r"(a[1]), "r"(a[2]), "r"(a[3]), "r"(b[0]), "r"(b[1]));
}

__device__ __forceinline__ uint32_t smem_u32(const void* p) {
    return (uint32_t)__cvta_generic_to_shared(p);
}
#define CP_ASYNC16(dst_u32, src_ptr) \
    asm volatile("cp.async.cg.shared.global [%0], [%1], 16;" \
        :: "r"(dst_u32), "l"(src_ptr))
#define CP_ASYNC_COMMIT() asm volatile("cp.async.commit_group;" ::: "memory")
#define CP_ASYNC_WAIT0()  asm volatile("cp.async.wait_group 0;" ::: "memory")

// ---------------------------------------------------------------------------
// Kernel 0: split q1 AND q2 into hi/lo bf16 (done once)
// ---------------------------------------------------------------------------
__global__ void k_split(const float* __restrict__ q1, const float* __restrict__ q2) {
    int gidx = blockIdx.x * 256 + threadIdx.x;   // 0 .. 524287
    int which = gidx >> 18;                      // 0 = q1, 1 = q2
    int idx = gidx & 0x3FFFF;                    // 0 .. 262143 float4 groups
    const float* src = which ? q2 : q1;
    float4 v = *(const float4*)(src + (size_t)idx * 4);
    __nv_bfloat16 h0 = __float2bfloat16(v.x), h1 = __float2bfloat16(v.y);
    __nv_bfloat16 h2 = __float2bfloat16(v.z), h3 = __float2bfloat16(v.w);
    __nv_bfloat16 l0 = __float2bfloat16(v.x - __bfloat162float(h0));
    __nv_bfloat16 l1 = __float2bfloat16(v.y - __bfloat162float(h1));
    __nv_bfloat16 l2 = __float2bfloat16(v.z - __bfloat162float(h2));
    __nv_bfloat16 l3 = __float2bfloat16(v.w - __bfloat162float(h3));
    uint2 pk;
    pk.x = ((uint32_t)__bfloat16_as_ushort(h1) << 16) | __bfloat16_as_ushort(h0);
    pk.y = ((uint32_t)__bfloat16_as_ushort(h3) << 16) | __bfloat16_as_ushort(h2);
    ((uint2*)(which ? g_q2h : g_q1h))[idx] = pk;
    pk.x = ((uint32_t)__bfloat16_as_ushort(l1) << 16) | __bfloat16_as_ushort(l0);
    pk.y = ((uint32_t)__bfloat16_as_ushort(l3) << 16) | __bfloat16_as_ushort(l2);
    ((uint2*)(which ? g_q2l : g_q1l))[idx] = pk;
}

// ---------------------------------------------------------------------------
// Kernel 0.5: all norms, once. grid (16 b, 16 ig) x 256. Warp = row i.
// ---------------------------------------------------------------------------
__global__ void __launch_bounds__(256)
k_norms(const float* __restrict__ q1, const float* __restrict__ q2,
        const float* __restrict__ W) {
    __shared__ float w2s[2][16][256];   // 32 KB
    int b = blockIdx.x, ig = blockIdx.y;
    int t = threadIdx.x, wid = t >> 5, lane = t & 31;

    for (int c = t; c < 8192; c += 256) {
        int dirp = c >> 8;              // dir*16+p
        int h = c & 255;
        float w = W[(size_t)(32 + dirp) * 256 + h];
        w2s[dirp >> 4][dirp & 15][h] = w * w;
    }
    __syncthreads();

    int i = ig * 8 + wid;
    for (int dir = 0; dir < 2; dir++) {
        const float* r1 = q1 + ((size_t)b * 128 + i) * 512 + dir * 256;
        const float* r2 = q2 + ((size_t)b * 128 + i) * 512 + dir * 256;
        float vv1[8], vv2[8];
        float s1 = 0.f, s2 = 0.f;
#pragma unroll
        for (int j = 0; j < 8; j++) {
            float a = r1[lane + 32 * j]; vv1[j] = a * a; s1 += vv1[j];
            float c = r2[lane + 32 * j]; vv2[j] = c * c; s2 += vv2[j];
        }
#pragma unroll
        for (int off = 16; off; off >>= 1) {
            s1 += __shfl_xor_sync(0xffffffffu, s1, off);
            s2 += __shfl_xor_sync(0xffffffffu, s2, off);
        }
        if (lane == 0) { g_n1[dir][b][i] = sqrtf(s1); g_n2[dir][b][i] = sqrtf(s2); }
#pragma unroll 2
        for (int p = 0; p < 16; p++) {
            float t1 = 0.f, t2 = 0.f;
#pragma unroll
            for (int j = 0; j < 8; j++) {
                float w = w2s[dir][p][lane + 32 * j];
                t1 += vv1[j] * w; t2 += vv2[j] * w;
            }
#pragma unroll
            for (int off = 16; off; off >>= 1) {
                t1 += __shfl_xor_sync(0xffffffffu, t1, off);
                t2 += __shfl_xor_sync(0xffffffffu, t2, off);
            }
            if (lane == 0) {
                g_wn1[dir][p][b][i] = sqrtf(t1);
                g_wn2[dir][p][b][i] = sqrtf(t2);
            }
        }
    }
}

// ---------------------------------------------------------------------------
// Shared tile geometry
// ---------------------------------------------------------------------------
#define TS_W    36                       // padded tile stride in 32-bit words
#define TILE_B  (128 * TS_W * 4)         // 18432 bytes (128-row tile)
#define TILE32_B (32 * TS_W * 4)         // 4608 bytes (32-row tile)

// ---------------------------------------------------------------------------
// Kernel 1 (HMMA): attention + fused rowsum. M split 4 ways.
// grid (16 b, 2 dir, 4 ms). CTA tile 32x128. 8 warps, each 32x16.
// ---------------------------------------------------------------------------
#define AOFF_N1   0
#define AOFF_N2   256
#define AOFF_RED  1024
#define AOFF_AH   3072
#define AOFF_AL   (AOFF_AH + TILE32_B)
#define AOFF_BH   (AOFF_AH + 2 * TILE32_B)
#define AOFF_BL   (AOFF_AH + 2 * TILE32_B + TILE_B)
#define SMEM_ATT_TOTAL (AOFF_AH + 2 * TILE32_B + 2 * TILE_B)   // 49152

__global__ void __launch_bounds__(256)
k_attention_mma(const float* __restrict__ q1, const float* __restrict__ q2) {
    extern __shared__ char smem[];
    int b = blockIdx.x, dir = blockIdx.y, ms = blockIdx.z;
    int m0 = ms * 32;
    int t = threadIdx.x;
    int wid = t >> 5, lane = t & 31;
    int gid = lane >> 2, tig = lane & 3;
    int nbw = wid * 16;                   // warp col base (8 warps x 16 cols)

    float* n1_s = (float*)(smem + AOFF_N1);      // [32]
    float* n2_s = (float*)(smem + AOFF_N2);      // [128]
    float* red  = (float*)(smem + AOFF_RED);     // [32][8]
    uint32_t* Ah_w = (uint32_t*)(smem + AOFF_AH);
    uint32_t* Al_w = (uint32_t*)(smem + AOFF_AL);
    uint32_t* Bh_w = (uint32_t*)(smem + AOFF_BH);
    uint32_t* Bl_w = (uint32_t*)(smem + AOFF_BL);

    // precomputed norms
    if (t < 128) n2_s[t] = g_n2[dir][b][t];
    else if (t < 160) n1_s[t - 128] = g_n1[dir][b][m0 + t - 128];

    float acc[2][2][4] = {};

    const __nv_bfloat16* q1h_base = g_q1h + ((size_t)b * 128 + m0) * 512 + dir * 256;
    const __nv_bfloat16* q1l_base = g_q1l + ((size_t)b * 128 + m0) * 512 + dir * 256;
    const __nv_bfloat16* q2h_base = g_q2h + ((size_t)b * 128) * 512 + dir * 256;
    const __nv_bfloat16* q2l_base = g_q2l + ((size_t)b * 128) * 512 + dir * 256;

    for (int c = 0; c < 4; c++) {
        int kb = c * 64;
        // A chunk: 32 rows x 64 cols = 256 uint4 (cp.async.cg 16B)
        {
            int n = t >> 3;
            int kk = (t & 7) * 8;
            uint32_t woff = (uint32_t)n * TS_W + (uint32_t)(kk >> 1);
            CP_ASYNC16(smem_u32(Ah_w + woff), q1h_base + (size_t)n * 512 + kb + kk);
            CP_ASYNC16(smem_u32(Al_w + woff), q1l_base + (size_t)n * 512 + kb + kk);
        }
        // B chunk: 128 rows x 64 cols = 1024 uint4
#pragma unroll
        for (int r = 0; r < 4; r++) {
            int v = r * 256 + t;
            int n = v >> 3;
            int kk = (v & 7) * 8;
            uint32_t woff = (uint32_t)n * TS_W + (uint32_t)(kk >> 1);
            CP_ASYNC16(smem_u32(Bh_w + woff), q2h_base + (size_t)n * 512 + kb + kk);
            CP_ASYNC16(smem_u32(Bl_w + woff), q2l_base + (size_t)n * 512 + kb + kk);
        }
        CP_ASYNC_COMMIT();
        CP_ASYNC_WAIT0();
        __syncthreads();

#pragma unroll
        for (int ks = 0; ks < 4; ks++) {
            int kw = ks * 8;
            uint32_t bhf[2][2], blf[2][2];
#pragma unroll
            for (int ni = 0; ni < 2; ni++) {
                const uint32_t* ph = Bh_w + (uint32_t)(nbw + ni * 8 + gid) * TS_W + kw + tig;
                bhf[ni][0] = ph[0]; bhf[ni][1] = ph[4];
                const uint32_t* pl = Bl_w + (uint32_t)(nbw + ni * 8 + gid) * TS_W + kw + tig;
                blf[ni][0] = pl[0]; blf[ni][1] = pl[4];
            }
#pragma unroll
            for (int mi = 0; mi < 2; mi++) {
                const uint32_t* pa = Ah_w + (uint32_t)(mi * 16 + gid) * TS_W + kw + tig;
                uint32_t ah[4];
                ah[0] = pa[0]; ah[1] = pa[8 * TS_W];
                ah[2] = pa[4]; ah[3] = pa[8 * TS_W + 4];
                const uint32_t* pl = Al_w + (uint32_t)(mi * 16 + gid) * TS_W + kw + tig;
                uint32_t al[4];
                al[0] = pl[0]; al[1] = pl[8 * TS_W];
                al[2] = pl[4]; al[3] = pl[8 * TS_W + 4];
#pragma unroll
                for (int ni = 0; ni < 2; ni++) {
                    mma16816(acc[mi][ni], ah, bhf[ni]);
                    mma16816(acc[mi][ni], ah, blf[ni]);
                    mma16816(acc[mi][ni], al, bhf[ni]);
                }
            }
        }
        __syncthreads();
    }

    // ---- epilogue: normalize, store att, fused rowsum ----
    float n2v[2][2];
#pragma unroll
    for (int ni = 0; ni < 2; ni++) {
        int cb = nbw + ni * 8 + 2 * tig;
        n2v[ni][0] = n2_s[cb];
        n2v[ni][1] = n2_s[cb + 1];
    }
#pragma unroll
    for (int mi = 0; mi < 2; mi++) {
        int rloc = mi * 16 + gid;
        float na0 = n1_s[rloc], na1 = n1_s[rloc + 8];
        float s0 = 0.f, s1 = 0.f;
#pragma unroll
        for (int ni = 0; ni < 2; ni++) {
            int cb = nbw + ni * 8 + 2 * tig;
            float d00 = na0 * n2v[ni][0]; d00 = (d00 > EPS) ? d00 : EPS;
            float d01 = na0 * n2v[ni][1]; d01 = (d01 > EPS) ? d01 : EPS;
            float d10 = na1 * n2v[ni][0]; d10 = (d10 > EPS) ? d10 : EPS;
            float d11 = na1 * n2v[ni][1]; d11 = (d11 > EPS) ? d11 : EPS;
            float a00 = acc[mi][ni][0] / d00;
            float a01 = acc[mi][ni][1] / d01;
            float a10 = acc[mi][ni][2] / d10;
            float a11 = acc[mi][ni][3] / d11;
            *(float2*)&g_att[dir][b][m0 + rloc][cb]     = make_float2(a00, a01);
            *(float2*)&g_att[dir][b][m0 + rloc + 8][cb] = make_float2(a10, a11);
            s0 += a00 + a01;
            s1 += a10 + a11;
        }
        s0 += __shfl_xor_sync(0xffffffffu, s0, 1);
        s0 += __shfl_xor_sync(0xffffffffu, s0, 2);
        s1 += __shfl_xor_sync(0xffffffffu, s1, 1);
        s1 += __shfl_xor_sync(0xffffffffu, s1, 2);
        if (tig == 0) {
            red[rloc * 8 + wid] = s0;
            red[(rloc + 8) * 8 + wid] = s1;
        }
    }
    __syncthreads();
    if (dir == 0 && t < 32) {
        float s = 0.f;
#pragma unroll
        for (int w = 0; w < 8; w++) s += red[t * 8 + w];
        g_rowsum_fw[b][m0 + t] = s;
    }
}

// ---------------------------------------------------------------------------
// Kernel 2: meanS / maxat — j-outer, register accumulators.
// ---------------------------------------------------------------------------
__global__ void __launch_bounds__(256)
k_meanmax(const float* __restrict__ q2) {
    int b = blockIdx.x, dir = blockIdx.y, iq = blockIdx.z;
    int i0 = iq * 8;
    __shared__ float2 att_s[8][64];

    const float* src = &g_att[dir][b][i0][0];
    {
        int c = threadIdx.x;
        float4 v0 = *(const float4*)(src + c * 4);
        ((float4*)att_s)[c] = v0;
    }
    __syncthreads();

    int h = threadIdx.x;
    const float* B = q2 + (size_t)b * 65536 + dir * 256 + h;

    float acc[8] = {};
    float mx[8] = {-INFINITY, -INFINITY, -INFINITY, -INFINITY,
                   -INFINITY, -INFINITY, -INFINITY, -INFINITY};

#pragma unroll 4
    for (int j2 = 0; j2 < 64; j2++) {
        float q0 = __ldg(B + (size_t)(2 * j2) * 512);
        float q1 = __ldg(B + (size_t)(2 * j2 + 1) * 512);
#pragma unroll
        for (int i = 0; i < 8; i++) {
            float2 a = att_s[i][j2];
            float v0 = a.x * q0;
            float v1 = a.y * q1;
            acc[i] += v0 + v1;
            mx[i] = fmaxf(mx[i], fmaxf(v0, v1));
        }
    }

#pragma unroll
    for (int i = 0; i < 8; i++) {
        g_meanS[dir][b][i0 + i][h] = acc[i];
        g_maxat[dir][b][i0 + i][h] = mx[i];
    }
}

// ---------------------------------------------------------------------------
// Kernel 3 (HMMA): cos_maxpool. One CTA per (b,p,dir), M=128, 2 CTAs/SM.
// Norms precomputed; B via cp.async.cg overlapped with A conversion.
// ---------------------------------------------------------------------------
#define OFF_W2   0
#define OFF_NA   1024
#define OFF_NC   1536
#define OFF_RED  2048
#define OFF_AH   4096
#define OFF_AL   (OFF_AH + TILE_B)
#define OFF_BH   (OFF_AH + 2 * TILE_B)
#define OFF_BL   (OFF_AH + 3 * TILE_B)
#define SMEM_MMA_TOTAL (OFF_AH + 4 * TILE_B)   // 77824

__global__ void __launch_bounds__(256, 2)
k_maxpool_mma(const float* __restrict__ q1, const float* __restrict__ q2,
              const float* __restrict__ W, float* __restrict__ out) {
    extern __shared__ char smem[];
    int b = blockIdx.x, p = blockIdx.y, dir = blockIdx.z;
    int t = threadIdx.x;
    int wid = t >> 5, lane = t & 31;
    int gid = lane >> 2, tig = lane & 3;
    int wr = wid >> 2, wc = wid & 3;
    int mb = wr * 64, nb = wc * 32;

    const float* Ag = q1 + (size_t)b * 65536 + dir * 256;
    const float* Wp = W + (size_t)((2 + dir) * 16 + p) * 256;

    float* w2s  = (float*)(smem + OFF_W2);
    float* na_s = (float*)(smem + OFF_NA);
    float* nc_s = (float*)(smem + OFF_NC);
    float* red  = (float*)(smem + OFF_RED);
    uint32_t* Ah_w = (uint32_t*)(smem + OFF_AH);
    uint32_t* Al_w = (uint32_t*)(smem + OFF_AL);
    uint32_t* Bh_w = (uint32_t*)(smem + OFF_BH);
    uint32_t* Bl_w = (uint32_t*)(smem + OFF_BL);

    { float w = Wp[t]; w2s[t] = w * w; }
    // precomputed weighted norms
    if (t < 128) na_s[t] = g_wn1[dir][p][b][t];
    else nc_s[t - 128] = g_wn2[dir][p][b][t - 128];
    __syncthreads();

    float acc[4][4][4];
#pragma unroll
    for (int mi = 0; mi < 4; mi++)
#pragma unroll
        for (int ni = 0; ni < 4; ni++)
#pragma unroll
            for (int c = 0; c < 4; c++) acc[mi][ni][c] = 0.f;

    const __nv_bfloat16* q2h_base = g_q2h + ((size_t)b * 128) * 512 + dir * 256;
    const __nv_bfloat16* q2l_base = g_q2l + ((size_t)b * 128) * 512 + dir * 256;

    for (int c = 0; c < 4; c++) {
        int kb = c * 64;
        // ---- issue cp.async.cg for B chunk first (overlaps with A convert) ----
#pragma unroll
        for (int r = 0; r < 4; r++) {
            int v = r * 256 + t;
            int n = v >> 3;
            int kk = (v & 7) * 8;
            uint32_t woff = (uint32_t)n * TS_W + (uint32_t)(kk >> 1);
            CP_ASYNC16(smem_u32(Bh_w + woff), q2h_base + (size_t)n * 512 + kb + kk);
            CP_ASYNC16(smem_u32(Bl_w + woff), q2l_base + (size_t)n * 512 + kb + kk);
        }
        CP_ASYNC_COMMIT();

        // ---- convert A chunk (q1 .* w2), split hi/lo: 128 rows x 64 cols ----
#pragma unroll
        for (int r = 0; r < 8; r++) {
            int v = r * 256 + t;
            int i = v >> 4;
            int h4 = (v & 15) * 4;
            float4 qa = *(const float4*)(Ag + (size_t)i * 512 + kb + h4);
            float a0 = qa.x * w2s[kb + h4 + 0];
            float a1 = qa.y * w2s[kb + h4 + 1];
            float a2 = qa.z * w2s[kb + h4 + 2];
            float a3 = qa.w * w2s[kb + h4 + 3];
            __nv_bfloat16 h0 = __float2bfloat16(a0), h1 = __float2bfloat16(a1);
            __nv_bfloat16 h2 = __float2bfloat16(a2), h3 = __float2bfloat16(a3);
            __nv_bfloat16 l0 = __float2bfloat16(a0 - __bfloat162float(h0));
            __nv_bfloat16 l1 = __float2bfloat16(a1 - __bfloat162float(h1));
            __nv_bfloat16 l2 = __float2bfloat16(a2 - __bfloat162float(h2));
            __nv_bfloat16 l3 = __float2bfloat16(a3 - __bfloat162float(h3));
            uint32_t woff = (uint32_t)i * TS_W + (uint32_t)(h4 >> 1);
            uint2 pk;
            pk.x = ((uint32_t)__bfloat16_as_ushort(h1) << 16) | __bfloat16_as_ushort(h0);
            pk.y = ((uint32_t)__bfloat16_as_ushort(h3) << 16) | __bfloat16_as_ushort(h2);
            *(uint2*)(Ah_w + woff) = pk;
            pk.x = ((uint32_t)__bfloat16_as_ushort(l1) << 16) | __bfloat16_as_ushort(l0);
            pk.y = ((uint32_t)__bfloat16_as_ushort(l3) << 16) | __bfloat16_as_ushort(l2);
            *(uint2*)(Al_w + woff) = pk;
        }
        CP_ASYNC_WAIT0();
        __syncthreads();

        // ---- MMA over this chunk: 4 k-steps of 16 ----
#pragma unroll
        for (int ks = 0; ks < 4; ks++) {
            int kw = ks * 8;
            uint32_t bhf[4][2], blf[4][2];
#pragma unroll
            for (int ni = 0; ni < 4; ni++) {
                const uint32_t* ph = Bh_w + (uint32_t)(nb + ni * 8 + gid) * TS_W + kw + tig;
                bhf[ni][0] = ph[0]; bhf[ni][1] = ph[4];
                const uint32_t* pl = Bl_w + (uint32_t)(nb + ni * 8 + gid) * TS_W + kw + tig;
                blf[ni][0] = pl[0]; blf[ni][1] = pl[4];
            }
#pragma unroll
            for (int mi = 0; mi < 4; mi++) {
                const uint32_t* pa = Ah_w + (uint32_t)(mb + mi * 16 + gid) * TS_W + kw + tig;
                uint32_t ah[4];
                ah[0] = pa[0]; ah[1] = pa[8 * TS_W];
                ah[2] = pa[4]; ah[3] = pa[8 * TS_W + 4];
                const uint32_t* pl = Al_w + (uint32_t)(mb + mi * 16 + gid) * TS_W + kw + tig;
                uint32_t al[4];
                al[0] = pl[0]; al[1] = pl[8 * TS_W];
                al[2] = pl[4]; al[3] = pl[8 * TS_W + 4];
#pragma unroll
                for (int ni = 0; ni < 4; ni++) {
                    mma16816(acc[mi][ni], ah, bhf[ni]);
                    mma16816(acc[mi][ni], ah, blf[ni]);
                    mma16816(acc[mi][ni], al, bhf[ni]);
                }
            }
        }
        __syncthreads();
    }

    // ---- epilogue: cos divide + row max ----
    float nc_v[4][2];
#pragma unroll
    for (int ni = 0; ni < 4; ni++) {
        int cb = nb + ni * 8 + 2 * tig;
        nc_v[ni][0] = nc_s[cb];
        nc_v[ni][1] = nc_s[cb + 1];
    }
#pragma unroll
    for (int mi = 0; mi < 4; mi++) {
        int r0 = mb + mi * 16 + gid;
        float na0 = na_s[r0], na1 = na_s[r0 + 8];
        float m0 = -INFINITY, m1 = -INFINITY;
#pragma unroll
        for (int ni = 0; ni < 4; ni++) {
            m0 = fmaxf(m0, acc[mi][ni][0] / fmaxf(na0 * nc_v[ni][0], EPS));
            m0 = fmaxf(m0, acc[mi][ni][1] / fmaxf(na0 * nc_v[ni][1], EPS));
            m1 = fmaxf(m1, acc[mi][ni][2] / fmaxf(na1 * nc_v[ni][0], EPS));
            m1 = fmaxf(m1, acc[mi][ni][3] / fmaxf(na1 * nc_v[ni][1], EPS));
        }
        m0 = fmaxf(m0, __shfl_xor_sync(0xffffffffu, m0, 1));
        m0 = fmaxf(m0, __shfl_xor_sync(0xffffffffu, m0, 2));
        m1 = fmaxf(m1, __shfl_xor_sync(0xffffffffu, m1, 1));
        m1 = fmaxf(m1, __shfl_xor_sync(0xffffffffu, m1, 2));
        if (tig == 0) {
            red[r0 * 4 + wc] = m0;
            red[(r0 + 8) * 4 + wc] = m1;
        }
    }
    __syncthreads();
    if (t < 128) {
        float m = red[t * 4 + 0];
        m = fmaxf(m, red[t * 4 + 1]);
        m = fmaxf(m, red[t * 4 + 2]);
        m = fmaxf(m, red[t * 4 + 3]);
        out[((size_t)b * 128 + t) * 128 + 32 + dir * 16 + p] = m;
    }
}

// ---------------------------------------------------------------------------
// Kernel 4: the six cos_full outputs
// ---------------------------------------------------------------------------
__global__ void k_cosfull(const float* __restrict__ q1, const float* __restrict__ q2,
                          const float* __restrict__ W, float* __restrict__ out) {
    int i = blockIdx.x, b = blockIdx.y;
    int lane = threadIdx.x & 31, warp = threadIdx.x >> 5;

    for (int s = 0; s < 12; s++) {
        int tk = warp + 8 * s;
        int p = tk & 15;
        int rest = tk >> 4;
        int dir = rest & 1, which = rest >> 1;
        int widx = (which == 0) ? dir : ((which == 1) ? 4 + dir : 6 + dir);
        const float* wv = W + (size_t)(widx * 16 + p) * 256;
        const float* x  = q1 + (size_t)b * 65536 + (size_t)i * 512 + dir * 256;
        const float* y;
        float sy = 1.f;
        if (which == 0) {
            int j = (dir == 0) ? 127 : 0;
            y = q2 + (size_t)b * 65536 + (size_t)j * 512 + dir * 256;
        } else if (which == 1) {
            y = &g_meanS[dir][b][i][0];
            float rs = g_rowsum_fw[b][i];
            float bsafe = (rs > EPS) ? rs : EPS;
            sy = 1.f / bsafe;
        } else {
            y = &g_maxat[dir][b][i][0];
        }

        float sxy = 0.f, sxx = 0.f, syy = 0.f;
        for (int h = lane; h < 256; h += 32) {
            float w = wv[h]; float ww = w * w;
            float xv = x[h];
            float yv = y[h] * sy;
            sxy += xv * yv * ww;
            sxx += xv * xv * ww;
            syy += yv * yv * ww;
        }
#pragma unroll
        for (int off = 16; off > 0; off >>= 1) {
            sxy += __shfl_xor_sync(0xffffffffu, sxy, off);
            sxx += __shfl_xor_sync(0xffffffffu, sxx, off);
            syy += __shfl_xor_sync(0xffffffffu, syy, off);
        }
        if (lane == 0) {
            float den = fmaxf(sqrtf(sxx) * sqrtf(syy), EPS);
            int col = ((which == 0) ? 0 : (which == 1) ? 64 : 96) + dir * 16 + p;
            out[((size_t)b * 128 + i) * 128 + col] = sxy / den;
        }
    }
}

// ---------------------------------------------------------------------------
extern "C" void kernel_launch(void* const* d_in, const int* in_sizes, int n_in,
                              void* d_out, int out_size) {
    const float* q1 = (const float*)d_in[0];
    const float* q2 = (const float*)d_in[1];
    const float* W  = (const float*)d_in[2];
    float* out = (float*)d_out;

    cudaFuncSetAttribute(k_attention_mma, cudaFuncAttributeMaxDynamicSharedMemorySize,
                         SMEM_ATT_TOTAL);
    cudaFuncSetAttribute(k_maxpool_mma, cudaFuncAttributeMaxDynamicSharedMemorySize,
                         SMEM_MMA_TOTAL);

    k_split<<<2048, 256>>>(q1, q2);
    k_norms<<<dim3(16, 16), 256>>>(q1, q2, W);
    k_attention_mma<<<dim3(16, 2, 4), 256, SMEM_ATT_TOTAL>>>(q1, q2);
    k_meanmax<<<dim3(16, 2, 16), 256>>>(q2);
    k_maxpool_mma<<<dim3(16, 16, 2), 256, SMEM_MMA_TOTAL>>>(q1, q2, W, out);
    k_cosfull<<<dim3(128, 16), 256>>>(q1, q2, W, out);
}